// round 16
// baseline (speedup 1.0000x reference)
#include <cuda_runtime.h>
#include <cuda_fp16.h>
#include <cuda_bf16.h>
#include <cuda_fp8.h>
#include <mma.h>
#include <cstdint>

using namespace nvcuda;

#define N_NODES 100000
#define N_TOTAL 150000
#define N_PAD   150016          // 1172 * 128
#define D_IN    512
#define H_LAT   256
#define N_CLASS 40
#define NNZ     4800000
#define NUM_LAYERS 3
#define CAP     96              // bucket capacity (Poisson(32): P(deg>=96) ~ 1e-18)

// ---------------- device scratch ----------------
__device__ float   g_acc  [(size_t)N_PAD   * H_LAT];
__device__ __half  g_curAh[(size_t)N_TOTAL * H_LAT];     // emb (fp16), layer-1 src
__device__ uint8_t g_cur8B[(size_t)N_TOTAL * H_LAT];     // l1 (fp8 x16), layer-2 src
__device__ uint8_t g_cur8A[(size_t)N_TOTAL * H_LAT];     // l2 (fp8 x16), layer-3 src
__device__ int     g_cnt  [N_TOTAL];
__device__ long long g_edge[(size_t)N_TOTAL * CAP];      // packed (val<<32)|col
__device__ __nv_bfloat16 g_Wh[(size_t)D_IN * H_LAT];     // W hi [k][n]
__device__ __nv_bfloat16 g_Wl[(size_t)D_IN * H_LAT];     // W lo [k][n]

// ---------------- bucket build ----------------
__global__ void zero_cnt_k() {
    int i = blockIdx.x * blockDim.x + threadIdx.x;
    if (i < N_TOTAL) g_cnt[i] = 0;
}

__global__ void scatter_k(const int* __restrict__ rows, const int* __restrict__ cols,
                          const float* __restrict__ vals) {
    int i = blockIdx.x * blockDim.x + threadIdx.x;
    if (i < NNZ) {
        int r = rows[i];
        int p = atomicAdd(&g_cnt[r], 1);
        if (p < CAP) {
            long long pk = ((long long)(unsigned)__float_as_uint(vals[i]) << 32)
                         | (unsigned)cols[i];
            g_edge[(size_t)r * CAP + p] = pk;
        }
    }
}

// ---------------- W preconvert: bf16 hi/lo, [k][n] layout ----------------
__global__ void wsplit_k(const float* __restrict__ W) {
    int i = blockIdx.x * blockDim.x + threadIdx.x;
    if (i >= D_IN * H_LAT) return;
    float w = W[i];
    __nv_bfloat16 h = __float2bfloat16_rn(w);
    __nv_bfloat16 l = __float2bfloat16_rn(w - __bfloat162float(h));
    g_Wh[i] = h;
    g_Wl[i] = l;
}

// ---------------- HMMA GEMM: emb = X @ W_red + b (3-term bf16 split) ----------------
// Known-good R6/R10 config: CTA 128x256, 512 threads (16 warps 4x4), K=32 stages,
// double buffer, reg-staged loads, fused bias + fp16 epilogue, acc node-rows-only.
#define GBK2 32
#define NCH2 (D_IN / GBK2)   // 16
#define ALD2 40              // 32 + 8 pad (bf16)
#define BLD  264             // 256 + 8 pad

#define SOFF_BIAS 0
#define SOFF_A    1024
#define A_HALF    (128 * ALD2 * 2)                // 10240
#define A_STAGE   (2 * A_HALF)                    // 20480
#define SOFF_B    (SOFF_A + 2 * A_STAGE)          // 41984
#define B_HALF    (GBK2 * BLD * 2)                // 16896
#define B_STAGE   (2 * B_HALF)                    // 33792
#define SMEM_GEMM (SOFF_B + 2 * B_STAGE)          // 109568

__global__ __launch_bounds__(512, 1) void gemm_w_k(const float* __restrict__ X,
                                                   const float* __restrict__ bias)
{
    extern __shared__ char smem[];
    float* bias_s = (float*)(smem + SOFF_BIAS);
    int tid  = threadIdx.x;
    int wid  = tid >> 5;
    int lane = tid & 31;
    int wm   = wid >> 2;     // 0..3 -> 32-row band
    int wn   = wid & 3;      // 0..3 -> 64-col band
    int m0   = blockIdx.x * 128;

    if (tid < 256) bias_s[tid] = bias[tid];

    int ar  = tid >> 2;            // 0..127 X row
    int ac8 = (tid & 3) * 8;       // k offset 0/8/16/24
    bool arow_ok = (m0 + ar) < N_TOTAL;
    const float* xrow = X + (size_t)(m0 + ar) * D_IN + ac8;
    int br   = tid >> 4;           // 0..31 k row
    int bc16 = (tid & 15) * 16;    // n offset
    const __nv_bfloat16* whp = g_Wh + (size_t)br * H_LAT + bc16;
    const __nv_bfloat16* wlp = g_Wl + (size_t)br * H_LAT + bc16;

    wmma::fragment<wmma::accumulator, 16, 16, 16, float> acc[2][4];
    #pragma unroll
    for (int i = 0; i < 2; i++)
        #pragma unroll
        for (int j = 0; j < 4; j++) wmma::fill_fragment(acc[i][j], 0.f);

    float4 xv0, xv1;
    uint4  whv0, whv1, wlv0, wlv1;

    if (arow_ok) { xv0 = *(const float4*)(xrow); xv1 = *(const float4*)(xrow + 4); }
    else { xv0 = make_float4(0.f,0.f,0.f,0.f); xv1 = xv0; }
    whv0 = *(const uint4*)(whp);     whv1 = *(const uint4*)(whp + 8);
    wlv0 = *(const uint4*)(wlp);     wlv1 = *(const uint4*)(wlp + 8);

    #define PACK8(dsth, dstl, a, b) do {                                          \
        __nv_bfloat16 h0 = __float2bfloat16_rn((a).x);                            \
        __nv_bfloat16 h1 = __float2bfloat16_rn((a).y);                            \
        __nv_bfloat16 h2 = __float2bfloat16_rn((a).z);                            \
        __nv_bfloat16 h3 = __float2bfloat16_rn((a).w);                            \
        __nv_bfloat16 h4 = __float2bfloat16_rn((b).x);                            \
        __nv_bfloat16 h5 = __float2bfloat16_rn((b).y);                            \
        __nv_bfloat16 h6 = __float2bfloat16_rn((b).z);                            \
        __nv_bfloat16 h7 = __float2bfloat16_rn((b).w);                            \
        __nv_bfloat16 l0 = __float2bfloat16_rn((a).x - __bfloat162float(h0));     \
        __nv_bfloat16 l1 = __float2bfloat16_rn((a).y - __bfloat162float(h1));     \
        __nv_bfloat16 l2 = __float2bfloat16_rn((a).z - __bfloat162float(h2));     \
        __nv_bfloat16 l3 = __float2bfloat16_rn((a).w - __bfloat162float(h3));     \
        __nv_bfloat16 l4 = __float2bfloat16_rn((b).x - __bfloat162float(h4));     \
        __nv_bfloat16 l5 = __float2bfloat16_rn((b).y - __bfloat162float(h5));     \
        __nv_bfloat16 l6 = __float2bfloat16_rn((b).z - __bfloat162float(h6));     \
        __nv_bfloat16 l7 = __float2bfloat16_rn((b).w - __bfloat162float(h7));     \
        unsigned short* hs = (unsigned short*)&(dsth);                            \
        unsigned short* ls = (unsigned short*)&(dstl);                            \
        hs[0]=*(unsigned short*)&h0; hs[1]=*(unsigned short*)&h1;                 \
        hs[2]=*(unsigned short*)&h2; hs[3]=*(unsigned short*)&h3;                 \
        hs[4]=*(unsigned short*)&h4; hs[5]=*(unsigned short*)&h5;                 \
        hs[6]=*(unsigned short*)&h6; hs[7]=*(unsigned short*)&h7;                 \
        ls[0]=*(unsigned short*)&l0; ls[1]=*(unsigned short*)&l1;                 \
        ls[2]=*(unsigned short*)&l2; ls[3]=*(unsigned short*)&l3;                 \
        ls[4]=*(unsigned short*)&l4; ls[5]=*(unsigned short*)&l5;                 \
        ls[6]=*(unsigned short*)&l6; ls[7]=*(unsigned short*)&l7;                 \
    } while (0)

    #define STORE_STAGE(s) do {                                                   \
        __nv_bfloat16* Ahp = (__nv_bfloat16*)(smem + SOFF_A + (s) * A_STAGE);     \
        __nv_bfloat16* Alp = (__nv_bfloat16*)(smem + SOFF_A + (s) * A_STAGE + A_HALF); \
        uint4 hp, lp;                                                             \
        PACK8(hp, lp, xv0, xv1);                                                  \
        *(uint4*)(Ahp + ar * ALD2 + ac8) = hp;                                    \
        *(uint4*)(Alp + ar * ALD2 + ac8) = lp;                                    \
        __nv_bfloat16* Bhp = (__nv_bfloat16*)(smem + SOFF_B + (s) * B_STAGE);     \
        __nv_bfloat16* Blp = (__nv_bfloat16*)(smem + SOFF_B + (s) * B_STAGE + B_HALF); \
        *(uint4*)(Bhp + br * BLD + bc16)     = whv0;                              \
        *(uint4*)(Bhp + br * BLD + bc16 + 8) = whv1;                              \
        *(uint4*)(Blp + br * BLD + bc16)     = wlv0;                              \
        *(uint4*)(Blp + br * BLD + bc16 + 8) = wlv1;                              \
    } while (0)

    STORE_STAGE(0);
    __syncthreads();

    #pragma unroll 1
    for (int c = 0; c < NCH2; c++) {
        if (c + 1 < NCH2) {
            int k0 = (c + 1) * GBK2;
            if (arow_ok) {
                xv0 = *(const float4*)(xrow + k0);
                xv1 = *(const float4*)(xrow + k0 + 4);
            } else { xv0 = make_float4(0.f,0.f,0.f,0.f); xv1 = xv0; }
            const __nv_bfloat16* wh = whp + (size_t)k0 * H_LAT;
            const __nv_bfloat16* wl = wlp + (size_t)k0 * H_LAT;
            whv0 = *(const uint4*)(wh);     whv1 = *(const uint4*)(wh + 8);
            wlv0 = *(const uint4*)(wl);     wlv1 = *(const uint4*)(wl + 8);
        }

        const __nv_bfloat16* Ahp = (const __nv_bfloat16*)(smem + SOFF_A + (c & 1) * A_STAGE);
        const __nv_bfloat16* Alp = (const __nv_bfloat16*)(smem + SOFF_A + (c & 1) * A_STAGE + A_HALF);
        const __nv_bfloat16* Bhp = (const __nv_bfloat16*)(smem + SOFF_B + (c & 1) * B_STAGE);
        const __nv_bfloat16* Blp = (const __nv_bfloat16*)(smem + SOFF_B + (c & 1) * B_STAGE + B_HALF);

        #pragma unroll
        for (int ks = 0; ks < 2; ks++) {
            wmma::fragment<wmma::matrix_a, 16, 16, 16, __nv_bfloat16, wmma::row_major> ah[2], al[2];
            #pragma unroll
            for (int im = 0; im < 2; im++) {
                wmma::load_matrix_sync(ah[im], Ahp + (wm * 32 + im * 16) * ALD2 + ks * 16, ALD2);
                wmma::load_matrix_sync(al[im], Alp + (wm * 32 + im * 16) * ALD2 + ks * 16, ALD2);
            }
            #pragma unroll
            for (int jn = 0; jn < 4; jn++) {
                wmma::fragment<wmma::matrix_b, 16, 16, 16, __nv_bfloat16, wmma::row_major> bh, bl;
                wmma::load_matrix_sync(bh, Bhp + ks * 16 * BLD + wn * 64 + jn * 16, BLD);
                wmma::load_matrix_sync(bl, Blp + ks * 16 * BLD + wn * 64 + jn * 16, BLD);
                #pragma unroll
                for (int im = 0; im < 2; im++) {
                    wmma::mma_sync(acc[im][jn], ah[im], bh, acc[im][jn]);
                    wmma::mma_sync(acc[im][jn], ah[im], bl, acc[im][jn]);
                    wmma::mma_sync(acc[im][jn], al[im], bh, acc[im][jn]);
                }
            }
        }

        if (c + 1 < NCH2) {
            STORE_STAGE((c + 1) & 1);
            __syncthreads();
        }
    }
    __syncthreads();

    // epilogue: per-warp smem scratch, bias + dual store (acc node-rows-only)
    float* scr = (float*)(smem + SOFF_A + wid * 1088);
    int r  = lane >> 1;        // 0..15
    int c8 = (lane & 1) * 8;   // 0/8
    #pragma unroll
    for (int im = 0; im < 2; im++) {
        #pragma unroll
        for (int jn = 0; jn < 4; jn++) {
            wmma::store_matrix_sync(scr, acc[im][jn], 16, wmma::mem_row_major);
            __syncwarp();
            float4 v0 = *(float4*)(scr + r * 16 + c8);
            float4 v1 = *(float4*)(scr + r * 16 + c8 + 4);
            int gcol = wn * 64 + jn * 16 + c8;
            v0.x += bias_s[gcol + 0]; v0.y += bias_s[gcol + 1];
            v0.z += bias_s[gcol + 2]; v0.w += bias_s[gcol + 3];
            v1.x += bias_s[gcol + 4]; v1.y += bias_s[gcol + 5];
            v1.z += bias_s[gcol + 6]; v1.w += bias_s[gcol + 7];
            int grow = m0 + wm * 32 + im * 16 + r;
            if (grow < N_NODES) {
                float* ap = g_acc + (size_t)grow * H_LAT + gcol;
                *(float4*)ap       = v0;
                *(float4*)(ap + 4) = v1;
            }
            if (grow < N_TOTAL) {
                __half2 p0 = __floats2half2_rn(v0.x, v0.y);
                __half2 p1 = __floats2half2_rn(v0.z, v0.w);
                __half2 p2 = __floats2half2_rn(v1.x, v1.y);
                __half2 p3 = __floats2half2_rn(v1.z, v1.w);
                uint4 pk;
                pk.x = *(unsigned*)&p0; pk.y = *(unsigned*)&p1;
                pk.z = *(unsigned*)&p2; pk.w = *(unsigned*)&p3;
                *(uint4*)(g_curAh + (size_t)grow * H_LAT + gcol) = pk;
            }
            __syncwarp();
        }
    }
}

// ---------------- SPMM helpers ----------------
// fp16 gather (layer 1)
__device__ __forceinline__ void accum_f16(const __half* __restrict__ src,
                                          const long long* __restrict__ ebase,
                                          int cnt, int off, float* s)
{
    int e = 0;
    for (; e + 2 <= cnt; e += 2) {
        long long p0 = ebase[e];
        long long p1 = ebase[e + 1];
        int   c0 = (int)(unsigned)(p0 & 0xffffffffll);
        int   c1 = (int)(unsigned)(p1 & 0xffffffffll);
        float v0 = __uint_as_float((unsigned)((unsigned long long)p0 >> 32));
        float v1 = __uint_as_float((unsigned)((unsigned long long)p1 >> 32));
        uint4 q0 = *(const uint4*)(src + (size_t)c0 * H_LAT + off);
        uint4 q1 = *(const uint4*)(src + (size_t)c1 * H_LAT + off);
        const __half2* h0 = (const __half2*)&q0;
        const __half2* h1 = (const __half2*)&q1;
        float2 f;
        f = __half22float2(h0[0]); s[0] = fmaf(v0, f.x, s[0]); s[1] = fmaf(v0, f.y, s[1]);
        f = __half22float2(h0[1]); s[2] = fmaf(v0, f.x, s[2]); s[3] = fmaf(v0, f.y, s[3]);
        f = __half22float2(h0[2]); s[4] = fmaf(v0, f.x, s[4]); s[5] = fmaf(v0, f.y, s[5]);
        f = __half22float2(h0[3]); s[6] = fmaf(v0, f.x, s[6]); s[7] = fmaf(v0, f.y, s[7]);
        f = __half22float2(h1[0]); s[0] = fmaf(v1, f.x, s[0]); s[1] = fmaf(v1, f.y, s[1]);
        f = __half22float2(h1[1]); s[2] = fmaf(v1, f.x, s[2]); s[3] = fmaf(v1, f.y, s[3]);
        f = __half22float2(h1[2]); s[4] = fmaf(v1, f.x, s[4]); s[5] = fmaf(v1, f.y, s[5]);
        f = __half22float2(h1[3]); s[6] = fmaf(v1, f.x, s[6]); s[7] = fmaf(v1, f.y, s[7]);
    }
    if (e < cnt) {
        long long p = ebase[e];
        int   c = (int)(unsigned)(p & 0xffffffffll);
        float v = __uint_as_float((unsigned)((unsigned long long)p >> 32));
        uint4 q = *(const uint4*)(src + (size_t)c * H_LAT + off);
        const __half2* h = (const __half2*)&q;
        float2 f;
        f = __half22float2(h[0]); s[0] = fmaf(v, f.x, s[0]); s[1] = fmaf(v, f.y, s[1]);
        f = __half22float2(h[1]); s[2] = fmaf(v, f.x, s[2]); s[3] = fmaf(v, f.y, s[3]);
        f = __half22float2(h[2]); s[4] = fmaf(v, f.x, s[4]); s[5] = fmaf(v, f.y, s[5]);
        f = __half22float2(h[3]); s[6] = fmaf(v, f.x, s[6]); s[7] = fmaf(v, f.y, s[7]);
    }
}

// fp8 (e4m3, x16-scaled) gather (layers 2,3): v pre-scaled by 1/16
__device__ __forceinline__ void dec8(unsigned w, float v, float* s, int base)
{
    __half2_raw r0 = __nv_cvt_fp8x2_to_halfraw2((__nv_fp8x2_storage_t)(w & 0xffffu), __NV_E4M3);
    __half2_raw r1 = __nv_cvt_fp8x2_to_halfraw2((__nv_fp8x2_storage_t)(w >> 16),     __NV_E4M3);
    float2 f0 = __half22float2(*(__half2*)&r0);
    float2 f1 = __half22float2(*(__half2*)&r1);
    s[base + 0] = fmaf(v, f0.x, s[base + 0]);
    s[base + 1] = fmaf(v, f0.y, s[base + 1]);
    s[base + 2] = fmaf(v, f1.x, s[base + 2]);
    s[base + 3] = fmaf(v, f1.y, s[base + 3]);
}

__device__ __forceinline__ void accum_f8(const uint8_t* __restrict__ src,
                                         const long long* __restrict__ ebase,
                                         int cnt, int off, float* s)
{
    int e = 0;
    for (; e + 2 <= cnt; e += 2) {
        long long p0 = ebase[e];
        long long p1 = ebase[e + 1];
        int   c0 = (int)(unsigned)(p0 & 0xffffffffll);
        int   c1 = (int)(unsigned)(p1 & 0xffffffffll);
        float v0 = __uint_as_float((unsigned)((unsigned long long)p0 >> 32)) * 0.0625f;
        float v1 = __uint_as_float((unsigned)((unsigned long long)p1 >> 32)) * 0.0625f;
        uint2 q0 = *(const uint2*)(src + (size_t)c0 * H_LAT + off);
        uint2 q1 = *(const uint2*)(src + (size_t)c1 * H_LAT + off);
        dec8(q0.x, v0, s, 0); dec8(q0.y, v0, s, 4);
        dec8(q1.x, v1, s, 0); dec8(q1.y, v1, s, 4);
    }
    if (e < cnt) {
        long long p = ebase[e];
        int   c = (int)(unsigned)(p & 0xffffffffll);
        float v = __uint_as_float((unsigned)((unsigned long long)p >> 32)) * 0.0625f;
        uint2 q = *(const uint2*)(src + (size_t)c * H_LAT + off);
        dec8(q.x, v, s, 0); dec8(q.y, v, s, 4);
    }
}

__device__ __forceinline__ uint2 pack_fp8x16(const float* s)
{
    uint8_t b[8];
    #pragma unroll
    for (int i = 0; i < 8; i++)
        b[i] = (uint8_t)__nv_cvt_float_to_fp8(s[i] * 16.f, __NV_SATFINITE, __NV_E4M3);
    uint2 r;
    r.x = (unsigned)b[0] | ((unsigned)b[1] << 8) | ((unsigned)b[2] << 16) | ((unsigned)b[3] << 24);
    r.y = (unsigned)b[4] | ((unsigned)b[5] << 8) | ((unsigned)b[6] << 16) | ((unsigned)b[7] << 24);
    return r;
}

__device__ __forceinline__ void acc_update(int gw, int off, const float* s)
{
    size_t o = (size_t)gw * H_LAT + off;
    float4* ap = (float4*)(g_acc + o);
    float4 a0 = __ldcs(ap);
    a0.x += s[0]; a0.y += s[1]; a0.z += s[2]; a0.w += s[3];
    __stcs(ap, a0);
    float4 a1 = __ldcs(ap + 1);
    a1.x += s[4]; a1.y += s[5]; a1.z += s[6]; a1.w += s[7];
    __stcs(ap + 1, a1);
}

// layer 1: fp16 src -> fp8 dst, acc node rows
__global__ __launch_bounds__(256) void spmm1_k()
{
    int gw   = (blockIdx.x * blockDim.x + threadIdx.x) >> 5;
    int lane = threadIdx.x & 31;
    if (gw >= N_TOTAL) return;
    int cnt = g_cnt[gw];
    if (cnt > CAP) cnt = CAP;
    const long long* ebase = g_edge + (size_t)gw * CAP;
    int off = lane * 8;

    float s[8] = {0.f,0.f,0.f,0.f,0.f,0.f,0.f,0.f};
    accum_f16(g_curAh, ebase, cnt, off, s);

    *(uint2*)(g_cur8B + (size_t)gw * H_LAT + off) = pack_fp8x16(s);
    if (gw < N_NODES) acc_update(gw, off, s);
}

// layer 2: fp8 src -> fp8 dst, acc node rows
__global__ __launch_bounds__(256) void spmm2_k()
{
    int gw   = (blockIdx.x * blockDim.x + threadIdx.x) >> 5;
    int lane = threadIdx.x & 31;
    if (gw >= N_TOTAL) return;
    int cnt = g_cnt[gw];
    if (cnt > CAP) cnt = CAP;
    const long long* ebase = g_edge + (size_t)gw * CAP;
    int off = lane * 8;

    float s[8] = {0.f,0.f,0.f,0.f,0.f,0.f,0.f,0.f};
    accum_f8(g_cur8B, ebase, cnt, off, s);

    *(uint2*)(g_cur8A + (size_t)gw * H_LAT + off) = pack_fp8x16(s);
    if (gw < N_NODES) acc_update(gw, off, s);
}

// layer 3: fp8 src, nodes only, acc only
__global__ __launch_bounds__(256) void spmm3_k()
{
    int gw   = (blockIdx.x * blockDim.x + threadIdx.x) >> 5;
    int lane = threadIdx.x & 31;
    if (gw >= N_NODES) return;
    int cnt = g_cnt[gw];
    if (cnt > CAP) cnt = CAP;
    const long long* ebase = g_edge + (size_t)gw * CAP;
    int off = lane * 8;

    float s[8] = {0.f,0.f,0.f,0.f,0.f,0.f,0.f,0.f};
    accum_f8(g_cur8A, ebase, cnt, off, s);
    acc_update(gw, off, s);
}

// ---------------- classifier + log_softmax ----------------
#define CR 64

__global__ __launch_bounds__(256) void cls_k(const float* __restrict__ Wc,
                                             const float* __restrict__ bc,
                                             float* __restrict__ out)
{
    __shared__ float Rt[64][68];
    __shared__ float Ws[64][68];
    int tid  = threadIdx.x;
    int row0 = blockIdx.x * CR;
    int r0   = (tid >> 4) * 4;
    int c0   = (tid & 15) * 4;

    float z[4][4];
    #pragma unroll
    for (int i = 0; i < 4; i++)
        #pragma unroll
        for (int j = 0; j < 4; j++) z[i][j] = 0.f;

    for (int ch = 0; ch < 4; ch++) {
        int h0 = ch * 64;
        #pragma unroll
        for (int i = 0; i < 4; i++) {
            int v  = tid + i * 256;
            int r  = v >> 4;
            int c4 = (v & 15) * 4;
            float4 a = make_float4(0.f, 0.f, 0.f, 0.f);
            int row = row0 + r;
            if (row < N_NODES) a = *(const float4*)(g_acc + (size_t)row * H_LAT + h0 + c4);
            Rt[c4 + 0][r] = a.x * 0.25f;
            Rt[c4 + 1][r] = a.y * 0.25f;
            Rt[c4 + 2][r] = a.z * 0.25f;
            Rt[c4 + 3][r] = a.w * 0.25f;
        }
        for (int i = tid; i < 64 * 40; i += 256) {
            int h = i / 40, c = i - h * 40;
            Ws[h][c] = Wc[(size_t)(h0 + h) * N_CLASS + c];
        }
        for (int i = tid; i < 64 * 24; i += 256) {
            int h = i / 24, c = 40 + (i - h * 24);
            Ws[h][c] = 0.f;
        }
        __syncthreads();

        #pragma unroll 4
        for (int h = 0; h < 64; h++) {
            float4 a = *(const float4*)&Rt[h][r0];
            float4 b = *(const float4*)&Ws[h][c0];
            float av[4] = {a.x, a.y, a.z, a.w};
            float bv[4] = {b.x, b.y, b.z, b.w};
            #pragma unroll
            for (int i = 0; i < 4; i++)
                #pragma unroll
                for (int j = 0; j < 4; j++)
                    z[i][j] = fmaf(av[i], bv[j], z[i][j]);
        }
        __syncthreads();
    }

    #pragma unroll
    for (int j = 0; j < 4; j++) {
        int c = c0 + j;
        float bj = (c < N_CLASS) ? bc[c] : 0.f;
        #pragma unroll
        for (int i = 0; i < 4; i++) {
            if (c < N_CLASS) z[i][j] += bj;
            else             z[i][j] = -1e30f;
        }
    }

    #pragma unroll
    for (int i = 0; i < 4; i++) {
        float m = fmaxf(fmaxf(z[i][0], z[i][1]), fmaxf(z[i][2], z[i][3]));
        #pragma unroll
        for (int d = 1; d < 16; d <<= 1)
            m = fmaxf(m, __shfl_xor_sync(0xffffffffu, m, d, 16));
        float s = 0.f;
        #pragma unroll
        for (int j = 0; j < 4; j++)
            s += (c0 + j < N_CLASS) ? __expf(z[i][j] - m) : 0.f;
        #pragma unroll
        for (int d = 1; d < 16; d <<= 1)
            s += __shfl_xor_sync(0xffffffffu, s, d, 16);
        float lse = m + __logf(s);
        int row = row0 + r0 + i;
        if (row < N_NODES) {
            #pragma unroll
            for (int j = 0; j < 4; j++) {
                int c = c0 + j;
                if (c < N_CLASS)
                    out[(size_t)row * N_CLASS + c] = z[i][j] - lse;
            }
        }
    }
}

// ---------------- launcher ----------------
extern "C" void kernel_launch(void* const* d_in, const int* in_sizes, int n_in,
                              void* d_out, int out_size)
{
    const float* X      = (const float*)d_in[0];
    const float* W_red  = (const float*)d_in[1];
    const float* b_red  = (const float*)d_in[2];
    const float* W_cls  = (const float*)d_in[3];
    const float* b_cls  = (const float*)d_in[4];
    const float* evals  = (const float*)d_in[5];
    const int*   erows  = (const int*)  d_in[6];
    const int*   ecols  = (const int*)  d_in[7];
    float* out = (float*)d_out;

    (void)in_sizes; (void)n_in; (void)out_size;

    cudaFuncSetAttribute(gemm_w_k, cudaFuncAttributeMaxDynamicSharedMemorySize, SMEM_GEMM);

    // bucketed edge build
    zero_cnt_k<<<(N_TOTAL + 255) / 256, 256>>>();
    scatter_k<<<(NNZ + 255) / 256, 256>>>(erows, ecols, evals);

    // W preconvert + HMMA GEMM (bias + fp16 fused)
    wsplit_k<<<(D_IN * H_LAT + 255) / 256, 256>>>(W_red);
    gemm_w_k<<<N_PAD / 128, 512, SMEM_GEMM>>>(X, b_red);

    // SPMM: layer1 fp16->fp8, layer2 fp8->fp8, layer3 fp8 nodes-only
    int full_blocks = (N_TOTAL * 32 + 255) / 256;
    int node_blocks = (N_NODES * 32 + 255) / 256;
    spmm1_k<<<full_blocks, 256>>>();
    spmm2_k<<<full_blocks, 256>>>();
    spmm3_k<<<node_blocks, 256>>>();

    // classifier + log_softmax
    cls_k<<<(N_NODES + CR - 1) / CR, 256>>>(W_cls, b_cls, out);
}

// round 17
// speedup vs baseline: 1.0019x; 1.0019x over previous
#include <cuda_runtime.h>
#include <cuda_fp16.h>
#include <cuda_bf16.h>
#include <cuda_fp8.h>
#include <mma.h>
#include <cstdint>

using namespace nvcuda;

#define N_NODES 100000
#define N_TOTAL 150000
#define N_PAD   150016          // 1172 * 128
#define D_IN    512
#define H_LAT   256
#define N_CLASS 40
#define NNZ     4800000
#define NUM_LAYERS 3
#define CAP     96              // bucket capacity (Poisson(32): P(deg>=96) ~ 1e-18)

// ---------------- device scratch ----------------
__device__ float   g_acc  [(size_t)N_PAD   * H_LAT];
__device__ __half  g_curAh[(size_t)N_TOTAL * H_LAT];     // emb (fp16), layer-1 src
__device__ uint8_t g_cur8B[(size_t)N_TOTAL * H_LAT];     // l1 (fp8 x16), layer-2 src
__device__ uint8_t g_cur8A[(size_t)N_TOTAL * H_LAT];     // l2 (fp8 x16), layer-3 src
__device__ int     g_cnt  [N_TOTAL];
__device__ long long g_edge[(size_t)N_TOTAL * CAP];      // packed (val<<32)|col
__device__ __nv_bfloat16 g_Wh[(size_t)D_IN * H_LAT];     // W hi [k][n]
__device__ __nv_bfloat16 g_Wl[(size_t)D_IN * H_LAT];     // W lo [k][n]

// ---------------- bucket build ----------------
__global__ void zero_cnt_k() {
    int i = blockIdx.x * blockDim.x + threadIdx.x;
    if (i < N_TOTAL) g_cnt[i] = 0;
}

__global__ void scatter_k(const int* __restrict__ rows, const int* __restrict__ cols,
                          const float* __restrict__ vals) {
    int i = blockIdx.x * blockDim.x + threadIdx.x;
    if (i < NNZ) {
        int r = rows[i];
        int p = atomicAdd(&g_cnt[r], 1);
        if (p < CAP) {
            long long pk = ((long long)(unsigned)__float_as_uint(vals[i]) << 32)
                         | (unsigned)cols[i];
            g_edge[(size_t)r * CAP + p] = pk;
        }
    }
}

// ---------------- W preconvert: bf16 hi/lo, [k][n] layout ----------------
__global__ void wsplit_k(const float* __restrict__ W) {
    int i = blockIdx.x * blockDim.x + threadIdx.x;
    if (i >= D_IN * H_LAT) return;
    float w = W[i];
    __nv_bfloat16 h = __float2bfloat16_rn(w);
    __nv_bfloat16 l = __float2bfloat16_rn(w - __bfloat162float(h));
    g_Wh[i] = h;
    g_Wl[i] = l;
}

// ---------------- HMMA GEMM: emb = X @ W_red + b (3-term bf16 split) ----------------
// Known-good R6/R10 config: CTA 128x256, 512 threads (16 warps 4x4), K=32 stages,
// double buffer, reg-staged loads, fused bias + fp16 epilogue, acc node-rows-only.
#define GBK2 32
#define NCH2 (D_IN / GBK2)   // 16
#define ALD2 40              // 32 + 8 pad (bf16)
#define BLD  264             // 256 + 8 pad

#define SOFF_BIAS 0
#define SOFF_A    1024
#define A_HALF    (128 * ALD2 * 2)                // 10240
#define A_STAGE   (2 * A_HALF)                    // 20480
#define SOFF_B    (SOFF_A + 2 * A_STAGE)          // 41984
#define B_HALF    (GBK2 * BLD * 2)                // 16896
#define B_STAGE   (2 * B_HALF)                    // 33792
#define SMEM_GEMM (SOFF_B + 2 * B_STAGE)          // 109568

__global__ __launch_bounds__(512, 1) void gemm_w_k(const float* __restrict__ X,
                                                   const float* __restrict__ bias)
{
    extern __shared__ char smem[];
    float* bias_s = (float*)(smem + SOFF_BIAS);
    int tid  = threadIdx.x;
    int wid  = tid >> 5;
    int lane = tid & 31;
    int wm   = wid >> 2;     // 0..3 -> 32-row band
    int wn   = wid & 3;      // 0..3 -> 64-col band
    int m0   = blockIdx.x * 128;

    if (tid < 256) bias_s[tid] = bias[tid];

    int ar  = tid >> 2;            // 0..127 X row
    int ac8 = (tid & 3) * 8;       // k offset 0/8/16/24
    bool arow_ok = (m0 + ar) < N_TOTAL;
    const float* xrow = X + (size_t)(m0 + ar) * D_IN + ac8;
    int br   = tid >> 4;           // 0..31 k row
    int bc16 = (tid & 15) * 16;    // n offset
    const __nv_bfloat16* whp = g_Wh + (size_t)br * H_LAT + bc16;
    const __nv_bfloat16* wlp = g_Wl + (size_t)br * H_LAT + bc16;

    wmma::fragment<wmma::accumulator, 16, 16, 16, float> acc[2][4];
    #pragma unroll
    for (int i = 0; i < 2; i++)
        #pragma unroll
        for (int j = 0; j < 4; j++) wmma::fill_fragment(acc[i][j], 0.f);

    float4 xv0, xv1;
    uint4  whv0, whv1, wlv0, wlv1;

    if (arow_ok) { xv0 = *(const float4*)(xrow); xv1 = *(const float4*)(xrow + 4); }
    else { xv0 = make_float4(0.f,0.f,0.f,0.f); xv1 = xv0; }
    whv0 = *(const uint4*)(whp);     whv1 = *(const uint4*)(whp + 8);
    wlv0 = *(const uint4*)(wlp);     wlv1 = *(const uint4*)(wlp + 8);

    #define PACK8(dsth, dstl, a, b) do {                                          \
        __nv_bfloat16 h0 = __float2bfloat16_rn((a).x);                            \
        __nv_bfloat16 h1 = __float2bfloat16_rn((a).y);                            \
        __nv_bfloat16 h2 = __float2bfloat16_rn((a).z);                            \
        __nv_bfloat16 h3 = __float2bfloat16_rn((a).w);                            \
        __nv_bfloat16 h4 = __float2bfloat16_rn((b).x);                            \
        __nv_bfloat16 h5 = __float2bfloat16_rn((b).y);                            \
        __nv_bfloat16 h6 = __float2bfloat16_rn((b).z);                            \
        __nv_bfloat16 h7 = __float2bfloat16_rn((b).w);                            \
        __nv_bfloat16 l0 = __float2bfloat16_rn((a).x - __bfloat162float(h0));     \
        __nv_bfloat16 l1 = __float2bfloat16_rn((a).y - __bfloat162float(h1));     \
        __nv_bfloat16 l2 = __float2bfloat16_rn((a).z - __bfloat162float(h2));     \
        __nv_bfloat16 l3 = __float2bfloat16_rn((a).w - __bfloat162float(h3));     \
        __nv_bfloat16 l4 = __float2bfloat16_rn((b).x - __bfloat162float(h4));     \
        __nv_bfloat16 l5 = __float2bfloat16_rn((b).y - __bfloat162float(h5));     \
        __nv_bfloat16 l6 = __float2bfloat16_rn((b).z - __bfloat162float(h6));     \
        __nv_bfloat16 l7 = __float2bfloat16_rn((b).w - __bfloat162float(h7));     \
        unsigned short* hs = (unsigned short*)&(dsth);                            \
        unsigned short* ls = (unsigned short*)&(dstl);                            \
        hs[0]=*(unsigned short*)&h0; hs[1]=*(unsigned short*)&h1;                 \
        hs[2]=*(unsigned short*)&h2; hs[3]=*(unsigned short*)&h3;                 \
        hs[4]=*(unsigned short*)&h4; hs[5]=*(unsigned short*)&h5;                 \
        hs[6]=*(unsigned short*)&h6; hs[7]=*(unsigned short*)&h7;                 \
        ls[0]=*(unsigned short*)&l0; ls[1]=*(unsigned short*)&l1;                 \
        ls[2]=*(unsigned short*)&l2; ls[3]=*(unsigned short*)&l3;                 \
        ls[4]=*(unsigned short*)&l4; ls[5]=*(unsigned short*)&l5;                 \
        ls[6]=*(unsigned short*)&l6; ls[7]=*(unsigned short*)&l7;                 \
    } while (0)

    #define STORE_STAGE(s) do {                                                   \
        __nv_bfloat16* Ahp = (__nv_bfloat16*)(smem + SOFF_A + (s) * A_STAGE);     \
        __nv_bfloat16* Alp = (__nv_bfloat16*)(smem + SOFF_A + (s) * A_STAGE + A_HALF); \
        uint4 hp, lp;                                                             \
        PACK8(hp, lp, xv0, xv1);                                                  \
        *(uint4*)(Ahp + ar * ALD2 + ac8) = hp;                                    \
        *(uint4*)(Alp + ar * ALD2 + ac8) = lp;                                    \
        __nv_bfloat16* Bhp = (__nv_bfloat16*)(smem + SOFF_B + (s) * B_STAGE);     \
        __nv_bfloat16* Blp = (__nv_bfloat16*)(smem + SOFF_B + (s) * B_STAGE + B_HALF); \
        *(uint4*)(Bhp + br * BLD + bc16)     = whv0;                              \
        *(uint4*)(Bhp + br * BLD + bc16 + 8) = whv1;                              \
        *(uint4*)(Blp + br * BLD + bc16)     = wlv0;                              \
        *(uint4*)(Blp + br * BLD + bc16 + 8) = wlv1;                              \
    } while (0)

    STORE_STAGE(0);
    __syncthreads();

    #pragma unroll 1
    for (int c = 0; c < NCH2; c++) {
        if (c + 1 < NCH2) {
            int k0 = (c + 1) * GBK2;
            if (arow_ok) {
                xv0 = *(const float4*)(xrow + k0);
                xv1 = *(const float4*)(xrow + k0 + 4);
            } else { xv0 = make_float4(0.f,0.f,0.f,0.f); xv1 = xv0; }
            const __nv_bfloat16* wh = whp + (size_t)k0 * H_LAT;
            const __nv_bfloat16* wl = wlp + (size_t)k0 * H_LAT;
            whv0 = *(const uint4*)(wh);     whv1 = *(const uint4*)(wh + 8);
            wlv0 = *(const uint4*)(wl);     wlv1 = *(const uint4*)(wl + 8);
        }

        const __nv_bfloat16* Ahp = (const __nv_bfloat16*)(smem + SOFF_A + (c & 1) * A_STAGE);
        const __nv_bfloat16* Alp = (const __nv_bfloat16*)(smem + SOFF_A + (c & 1) * A_STAGE + A_HALF);
        const __nv_bfloat16* Bhp = (const __nv_bfloat16*)(smem + SOFF_B + (c & 1) * B_STAGE);
        const __nv_bfloat16* Blp = (const __nv_bfloat16*)(smem + SOFF_B + (c & 1) * B_STAGE + B_HALF);

        #pragma unroll
        for (int ks = 0; ks < 2; ks++) {
            wmma::fragment<wmma::matrix_a, 16, 16, 16, __nv_bfloat16, wmma::row_major> ah[2], al[2];
            #pragma unroll
            for (int im = 0; im < 2; im++) {
                wmma::load_matrix_sync(ah[im], Ahp + (wm * 32 + im * 16) * ALD2 + ks * 16, ALD2);
                wmma::load_matrix_sync(al[im], Alp + (wm * 32 + im * 16) * ALD2 + ks * 16, ALD2);
            }
            #pragma unroll
            for (int jn = 0; jn < 4; jn++) {
                wmma::fragment<wmma::matrix_b, 16, 16, 16, __nv_bfloat16, wmma::row_major> bh, bl;
                wmma::load_matrix_sync(bh, Bhp + ks * 16 * BLD + wn * 64 + jn * 16, BLD);
                wmma::load_matrix_sync(bl, Blp + ks * 16 * BLD + wn * 64 + jn * 16, BLD);
                #pragma unroll
                for (int im = 0; im < 2; im++) {
                    wmma::mma_sync(acc[im][jn], ah[im], bh, acc[im][jn]);
                    wmma::mma_sync(acc[im][jn], ah[im], bl, acc[im][jn]);
                    wmma::mma_sync(acc[im][jn], al[im], bh, acc[im][jn]);
                }
            }
        }

        if (c + 1 < NCH2) {
            STORE_STAGE((c + 1) & 1);
            __syncthreads();
        }
    }
    __syncthreads();

    // epilogue: per-warp smem scratch, bias + dual store (acc node-rows-only)
    float* scr = (float*)(smem + SOFF_A + wid * 1088);
    int r  = lane >> 1;        // 0..15
    int c8 = (lane & 1) * 8;   // 0/8
    #pragma unroll
    for (int im = 0; im < 2; im++) {
        #pragma unroll
        for (int jn = 0; jn < 4; jn++) {
            wmma::store_matrix_sync(scr, acc[im][jn], 16, wmma::mem_row_major);
            __syncwarp();
            float4 v0 = *(float4*)(scr + r * 16 + c8);
            float4 v1 = *(float4*)(scr + r * 16 + c8 + 4);
            int gcol = wn * 64 + jn * 16 + c8;
            v0.x += bias_s[gcol + 0]; v0.y += bias_s[gcol + 1];
            v0.z += bias_s[gcol + 2]; v0.w += bias_s[gcol + 3];
            v1.x += bias_s[gcol + 4]; v1.y += bias_s[gcol + 5];
            v1.z += bias_s[gcol + 6]; v1.w += bias_s[gcol + 7];
            int grow = m0 + wm * 32 + im * 16 + r;
            if (grow < N_NODES) {
                float* ap = g_acc + (size_t)grow * H_LAT + gcol;
                *(float4*)ap       = v0;
                *(float4*)(ap + 4) = v1;
            }
            if (grow < N_TOTAL) {
                __half2 p0 = __floats2half2_rn(v0.x, v0.y);
                __half2 p1 = __floats2half2_rn(v0.z, v0.w);
                __half2 p2 = __floats2half2_rn(v1.x, v1.y);
                __half2 p3 = __floats2half2_rn(v1.z, v1.w);
                uint4 pk;
                pk.x = *(unsigned*)&p0; pk.y = *(unsigned*)&p1;
                pk.z = *(unsigned*)&p2; pk.w = *(unsigned*)&p3;
                *(uint4*)(g_curAh + (size_t)grow * H_LAT + gcol) = pk;
            }
            __syncwarp();
        }
    }
}

// ---------------- SPMM helpers ----------------
// fp16 gather (layer 1)
__device__ __forceinline__ void accum_f16(const __half* __restrict__ src,
                                          const long long* __restrict__ ebase,
                                          int cnt, int off, float* s)
{
    int e = 0;
    for (; e + 2 <= cnt; e += 2) {
        long long p0 = ebase[e];
        long long p1 = ebase[e + 1];
        int   c0 = (int)(unsigned)(p0 & 0xffffffffll);
        int   c1 = (int)(unsigned)(p1 & 0xffffffffll);
        float v0 = __uint_as_float((unsigned)((unsigned long long)p0 >> 32));
        float v1 = __uint_as_float((unsigned)((unsigned long long)p1 >> 32));
        uint4 q0 = *(const uint4*)(src + (size_t)c0 * H_LAT + off);
        uint4 q1 = *(const uint4*)(src + (size_t)c1 * H_LAT + off);
        const __half2* h0 = (const __half2*)&q0;
        const __half2* h1 = (const __half2*)&q1;
        float2 f;
        f = __half22float2(h0[0]); s[0] = fmaf(v0, f.x, s[0]); s[1] = fmaf(v0, f.y, s[1]);
        f = __half22float2(h0[1]); s[2] = fmaf(v0, f.x, s[2]); s[3] = fmaf(v0, f.y, s[3]);
        f = __half22float2(h0[2]); s[4] = fmaf(v0, f.x, s[4]); s[5] = fmaf(v0, f.y, s[5]);
        f = __half22float2(h0[3]); s[6] = fmaf(v0, f.x, s[6]); s[7] = fmaf(v0, f.y, s[7]);
        f = __half22float2(h1[0]); s[0] = fmaf(v1, f.x, s[0]); s[1] = fmaf(v1, f.y, s[1]);
        f = __half22float2(h1[1]); s[2] = fmaf(v1, f.x, s[2]); s[3] = fmaf(v1, f.y, s[3]);
        f = __half22float2(h1[2]); s[4] = fmaf(v1, f.x, s[4]); s[5] = fmaf(v1, f.y, s[5]);
        f = __half22float2(h1[3]); s[6] = fmaf(v1, f.x, s[6]); s[7] = fmaf(v1, f.y, s[7]);
    }
    if (e < cnt) {
        long long p = ebase[e];
        int   c = (int)(unsigned)(p & 0xffffffffll);
        float v = __uint_as_float((unsigned)((unsigned long long)p >> 32));
        uint4 q = *(const uint4*)(src + (size_t)c * H_LAT + off);
        const __half2* h = (const __half2*)&q;
        float2 f;
        f = __half22float2(h[0]); s[0] = fmaf(v, f.x, s[0]); s[1] = fmaf(v, f.y, s[1]);
        f = __half22float2(h[1]); s[2] = fmaf(v, f.x, s[2]); s[3] = fmaf(v, f.y, s[3]);
        f = __half22float2(h[2]); s[4] = fmaf(v, f.x, s[4]); s[5] = fmaf(v, f.y, s[5]);
        f = __half22float2(h[3]); s[6] = fmaf(v, f.x, s[6]); s[7] = fmaf(v, f.y, s[7]);
    }
}

// fp8 (e4m3, x16-scaled) gather (layers 2,3): v pre-scaled by 1/16
__device__ __forceinline__ void dec8(unsigned w, float v, float* s, int base)
{
    __half2_raw r0 = __nv_cvt_fp8x2_to_halfraw2((__nv_fp8x2_storage_t)(w & 0xffffu), __NV_E4M3);
    __half2_raw r1 = __nv_cvt_fp8x2_to_halfraw2((__nv_fp8x2_storage_t)(w >> 16),     __NV_E4M3);
    float2 f0 = __half22float2(*(__half2*)&r0);
    float2 f1 = __half22float2(*(__half2*)&r1);
    s[base + 0] = fmaf(v, f0.x, s[base + 0]);
    s[base + 1] = fmaf(v, f0.y, s[base + 1]);
    s[base + 2] = fmaf(v, f1.x, s[base + 2]);
    s[base + 3] = fmaf(v, f1.y, s[base + 3]);
}

__device__ __forceinline__ void accum_f8(const uint8_t* __restrict__ src,
                                         const long long* __restrict__ ebase,
                                         int cnt, int off, float* s)
{
    int e = 0;
    for (; e + 2 <= cnt; e += 2) {
        long long p0 = ebase[e];
        long long p1 = ebase[e + 1];
        int   c0 = (int)(unsigned)(p0 & 0xffffffffll);
        int   c1 = (int)(unsigned)(p1 & 0xffffffffll);
        float v0 = __uint_as_float((unsigned)((unsigned long long)p0 >> 32)) * 0.0625f;
        float v1 = __uint_as_float((unsigned)((unsigned long long)p1 >> 32)) * 0.0625f;
        uint2 q0 = *(const uint2*)(src + (size_t)c0 * H_LAT + off);
        uint2 q1 = *(const uint2*)(src + (size_t)c1 * H_LAT + off);
        dec8(q0.x, v0, s, 0); dec8(q0.y, v0, s, 4);
        dec8(q1.x, v1, s, 0); dec8(q1.y, v1, s, 4);
    }
    if (e < cnt) {
        long long p = ebase[e];
        int   c = (int)(unsigned)(p & 0xffffffffll);
        float v = __uint_as_float((unsigned)((unsigned long long)p >> 32)) * 0.0625f;
        uint2 q = *(const uint2*)(src + (size_t)c * H_LAT + off);
        dec8(q.x, v, s, 0); dec8(q.y, v, s, 4);
    }
}

__device__ __forceinline__ uint2 pack_fp8x16(const float* s)
{
    uint8_t b[8];
    #pragma unroll
    for (int i = 0; i < 8; i++)
        b[i] = (uint8_t)__nv_cvt_float_to_fp8(s[i] * 16.f, __NV_SATFINITE, __NV_E4M3);
    uint2 r;
    r.x = (unsigned)b[0] | ((unsigned)b[1] << 8) | ((unsigned)b[2] << 16) | ((unsigned)b[3] << 24);
    r.y = (unsigned)b[4] | ((unsigned)b[5] << 8) | ((unsigned)b[6] << 16) | ((unsigned)b[7] << 24);
    return r;
}

__device__ __forceinline__ void acc_update(int gw, int off, const float* s)
{
    size_t o = (size_t)gw * H_LAT + off;
    float4* ap = (float4*)(g_acc + o);
    float4 a0 = __ldcs(ap);
    a0.x += s[0]; a0.y += s[1]; a0.z += s[2]; a0.w += s[3];
    __stcs(ap, a0);
    float4 a1 = __ldcs(ap + 1);
    a1.x += s[4]; a1.y += s[5]; a1.z += s[6]; a1.w += s[7];
    __stcs(ap + 1, a1);
}

// layer 1: fp16 src -> fp8 dst, acc node rows
__global__ __launch_bounds__(256) void spmm1_k()
{
    int gw   = (blockIdx.x * blockDim.x + threadIdx.x) >> 5;
    int lane = threadIdx.x & 31;
    if (gw >= N_TOTAL) return;
    int cnt = g_cnt[gw];
    if (cnt > CAP) cnt = CAP;
    const long long* ebase = g_edge + (size_t)gw * CAP;
    int off = lane * 8;

    float s[8] = {0.f,0.f,0.f,0.f,0.f,0.f,0.f,0.f};
    accum_f16(g_curAh, ebase, cnt, off, s);

    *(uint2*)(g_cur8B + (size_t)gw * H_LAT + off) = pack_fp8x16(s);
    if (gw < N_NODES) acc_update(gw, off, s);
}

// layer 2: fp8 src -> fp8 dst, acc node rows
__global__ __launch_bounds__(256) void spmm2_k()
{
    int gw   = (blockIdx.x * blockDim.x + threadIdx.x) >> 5;
    int lane = threadIdx.x & 31;
    if (gw >= N_TOTAL) return;
    int cnt = g_cnt[gw];
    if (cnt > CAP) cnt = CAP;
    const long long* ebase = g_edge + (size_t)gw * CAP;
    int off = lane * 8;

    float s[8] = {0.f,0.f,0.f,0.f,0.f,0.f,0.f,0.f};
    accum_f8(g_cur8B, ebase, cnt, off, s);

    *(uint2*)(g_cur8A + (size_t)gw * H_LAT + off) = pack_fp8x16(s);
    if (gw < N_NODES) acc_update(gw, off, s);
}

// layer 3: fp8 src, nodes only, acc only
__global__ __launch_bounds__(256) void spmm3_k()
{
    int gw   = (blockIdx.x * blockDim.x + threadIdx.x) >> 5;
    int lane = threadIdx.x & 31;
    if (gw >= N_NODES) return;
    int cnt = g_cnt[gw];
    if (cnt > CAP) cnt = CAP;
    const long long* ebase = g_edge + (size_t)gw * CAP;
    int off = lane * 8;

    float s[8] = {0.f,0.f,0.f,0.f,0.f,0.f,0.f,0.f};
    accum_f8(g_cur8A, ebase, cnt, off, s);
    acc_update(gw, off, s);
}

// ---------------- classifier + log_softmax ----------------
#define CR 64

__global__ __launch_bounds__(256) void cls_k(const float* __restrict__ Wc,
                                             const float* __restrict__ bc,
                                             float* __restrict__ out)
{
    __shared__ float Rt[64][68];
    __shared__ float Ws[64][68];
    int tid  = threadIdx.x;
    int row0 = blockIdx.x * CR;
    int r0   = (tid >> 4) * 4;
    int c0   = (tid & 15) * 4;

    float z[4][4];
    #pragma unroll
    for (int i = 0; i < 4; i++)
        #pragma unroll
        for (int j = 0; j < 4; j++) z[i][j] = 0.f;

    for (int ch = 0; ch < 4; ch++) {
        int h0 = ch * 64;
        #pragma unroll
        for (int i = 0; i < 4; i++) {
            int v  = tid + i * 256;
            int r  = v >> 4;
            int c4 = (v & 15) * 4;
            float4 a = make_float4(0.f, 0.f, 0.f, 0.f);
            int row = row0 + r;
            if (row < N_NODES) a = *(const float4*)(g_acc + (size_t)row * H_LAT + h0 + c4);
            Rt[c4 + 0][r] = a.x * 0.25f;
            Rt[c4 + 1][r] = a.y * 0.25f;
            Rt[c4 + 2][r] = a.z * 0.25f;
            Rt[c4 + 3][r] = a.w * 0.25f;
        }
        for (int i = tid; i < 64 * 40; i += 256) {
            int h = i / 40, c = i - h * 40;
            Ws[h][c] = Wc[(size_t)(h0 + h) * N_CLASS + c];
        }
        for (int i = tid; i < 64 * 24; i += 256) {
            int h = i / 24, c = 40 + (i - h * 24);
            Ws[h][c] = 0.f;
        }
        __syncthreads();

        #pragma unroll 4
        for (int h = 0; h < 64; h++) {
            float4 a = *(const float4*)&Rt[h][r0];
            float4 b = *(const float4*)&Ws[h][c0];
            float av[4] = {a.x, a.y, a.z, a.w};
            float bv[4] = {b.x, b.y, b.z, b.w};
            #pragma unroll
            for (int i = 0; i < 4; i++)
                #pragma unroll
                for (int j = 0; j < 4; j++)
                    z[i][j] = fmaf(av[i], bv[j], z[i][j]);
        }
        __syncthreads();
    }

    #pragma unroll
    for (int j = 0; j < 4; j++) {
        int c = c0 + j;
        float bj = (c < N_CLASS) ? bc[c] : 0.f;
        #pragma unroll
        for (int i = 0; i < 4; i++) {
            if (c < N_CLASS) z[i][j] += bj;
            else             z[i][j] = -1e30f;
        }
    }

    #pragma unroll
    for (int i = 0; i < 4; i++) {
        float m = fmaxf(fmaxf(z[i][0], z[i][1]), fmaxf(z[i][2], z[i][3]));
        #pragma unroll
        for (int d = 1; d < 16; d <<= 1)
            m = fmaxf(m, __shfl_xor_sync(0xffffffffu, m, d, 16));
        float s = 0.f;
        #pragma unroll
        for (int j = 0; j < 4; j++)
            s += (c0 + j < N_CLASS) ? __expf(z[i][j] - m) : 0.f;
        #pragma unroll
        for (int d = 1; d < 16; d <<= 1)
            s += __shfl_xor_sync(0xffffffffu, s, d, 16);
        float lse = m + __logf(s);
        int row = row0 + r0 + i;
        if (row < N_NODES) {
            #pragma unroll
            for (int j = 0; j < 4; j++) {
                int c = c0 + j;
                if (c < N_CLASS)
                    out[(size_t)row * N_CLASS + c] = z[i][j] - lse;
            }
        }
    }
}

// ---------------- launcher ----------------
extern "C" void kernel_launch(void* const* d_in, const int* in_sizes, int n_in,
                              void* d_out, int out_size)
{
    const float* X      = (const float*)d_in[0];
    const float* W_red  = (const float*)d_in[1];
    const float* b_red  = (const float*)d_in[2];
    const float* W_cls  = (const float*)d_in[3];
    const float* b_cls  = (const float*)d_in[4];
    const float* evals  = (const float*)d_in[5];
    const int*   erows  = (const int*)  d_in[6];
    const int*   ecols  = (const int*)  d_in[7];
    float* out = (float*)d_out;

    (void)in_sizes; (void)n_in; (void)out_size;

    cudaFuncSetAttribute(gemm_w_k, cudaFuncAttributeMaxDynamicSharedMemorySize, SMEM_GEMM);

    // bucketed edge build
    zero_cnt_k<<<(N_TOTAL + 255) / 256, 256>>>();
    scatter_k<<<(NNZ + 255) / 256, 256>>>(erows, ecols, evals);

    // W preconvert + HMMA GEMM (bias + fp16 fused)
    wsplit_k<<<(D_IN * H_LAT + 255) / 256, 256>>>(W_red);
    gemm_w_k<<<N_PAD / 128, 512, SMEM_GEMM>>>(X, b_red);

    // SPMM: layer1 fp16->fp8, layer2 fp8->fp8, layer3 fp8 nodes-only
    int full_blocks = (N_TOTAL * 32 + 255) / 256;
    int node_blocks = (N_NODES * 32 + 255) / 256;
    spmm1_k<<<full_blocks, 256>>>();
    spmm2_k<<<full_blocks, 256>>>();
    spmm3_k<<<node_blocks, 256>>>();

    // classifier + log_softmax
    cls_k<<<(N_NODES + CR - 1) / CR, 256>>>(W_cls, b_cls, out);
}